// round 3
// baseline (speedup 1.0000x reference)
#include <cuda_runtime.h>
#include <cstdint>

#define DIM 512
#define BM 128
#define BN 128
#define BK 16
#define TM 8
#define TN 4
#define THREADS 512          // (BM/TM) * (BN/TN) = 16 * 32
#define LDA (BM + 4)         // padded smem stride (keeps float4 16B alignment)
#define MAX_K 8192

__device__ float  g_enorm[MAX_K];
__device__ double g_loss_sum;

// ---------------------------------------------------------------------------
// prep: ||e_k||^2 per codebook row (one warp per row), and zero loss scratch.
// ---------------------------------------------------------------------------
__global__ void vq_prep_kernel(const float* __restrict__ ew, int K) {
    if (blockIdx.x == 0 && threadIdx.x == 0) g_loss_sum = 0.0;
    int warp = (blockIdx.x * blockDim.x + threadIdx.x) >> 5;
    int lane = threadIdx.x & 31;
    if (warp >= K) return;
    const float4* row = (const float4*)(ew + (size_t)warp * DIM);
    float s = 0.f;
#pragma unroll
    for (int it = 0; it < DIM / 128; ++it) {     // 512/4 floats / 32 lanes = 4 iters
        float4 v = row[lane + 32 * it];
        s += v.x * v.x + v.y * v.y + v.z * v.z + v.w * v.w;
    }
#pragma unroll
    for (int off = 16; off; off >>= 1) s += __shfl_xor_sync(0xffffffffu, s, off);
    if (lane == 0) g_enorm[warp] = s;
}

// ---------------------------------------------------------------------------
// main: fused distance-GEMM + argmin + gather + loss. One block per 128 rows.
// ---------------------------------------------------------------------------
__global__ __launch_bounds__(THREADS)
void vq_main_kernel(const float* __restrict__ xs,
                    const float* __restrict__ ew,
                    float* __restrict__ out,
                    int K) {
    __shared__ float As[BK * LDA];                 // x tile, [d][m] transposed
    __shared__ float Bs[BK * LDA];                 // e tile, [d][n] transposed
    __shared__ unsigned long long best[BM];        // (ordered_key << 32) | idx
    __shared__ double red[THREADS / 32];

    const int tid = threadIdx.x;
    const int tx  = tid & 31;                      // 32 column-groups of TN=4
    const int ty  = tid >> 5;                      // 16 row-groups of TM=8 (== warp id)
    const int rowBase = blockIdx.x * BM;
    const int lm = tid >> 2;                       // load row within tile (0..127)
    const int ld = (tid & 3) * 4;                  // load col offset (0,4,8,12)

    for (int i = tid; i < BM; i += THREADS) best[i] = ~0ull;
    __syncthreads();

    for (int n0 = 0; n0 < K; n0 += BN) {
        float acc[TM][TN];
#pragma unroll
        for (int i = 0; i < TM; ++i)
#pragma unroll
            for (int j = 0; j < TN; ++j) acc[i][j] = 0.f;

        for (int d0 = 0; d0 < DIM; d0 += BK) {
            // global -> smem (transposed)
            float4 xa = *(const float4*)(xs + (size_t)(rowBase + lm) * DIM + d0 + ld);
            float4 ea = *(const float4*)(ew + (size_t)(n0 + lm) * DIM + d0 + ld);
            As[(ld + 0) * LDA + lm] = xa.x;
            As[(ld + 1) * LDA + lm] = xa.y;
            As[(ld + 2) * LDA + lm] = xa.z;
            As[(ld + 3) * LDA + lm] = xa.w;
            Bs[(ld + 0) * LDA + lm] = ea.x;
            Bs[(ld + 1) * LDA + lm] = ea.y;
            Bs[(ld + 2) * LDA + lm] = ea.z;
            Bs[(ld + 3) * LDA + lm] = ea.w;
            __syncthreads();

#pragma unroll
            for (int k = 0; k < BK; ++k) {
                float4 a0 = *(const float4*)&As[k * LDA + ty * TM];
                float4 a1 = *(const float4*)&As[k * LDA + ty * TM + 4];
                float4 b  = *(const float4*)&Bs[k * LDA + tx * TN];
                float av[TM] = {a0.x, a0.y, a0.z, a0.w, a1.x, a1.y, a1.z, a1.w};
                float bv[TN] = {b.x, b.y, b.z, b.w};
#pragma unroll
                for (int i = 0; i < TM; ++i)
#pragma unroll
                    for (int j = 0; j < TN; ++j)
                        acc[i][j] = fmaf(av[i], bv[j], acc[i][j]);
            }
            __syncthreads();
        }

        // epilogue: score = ||e||^2 - 2 x.e, fold into per-row running argmin
        float4 en4 = *(const float4*)&g_enorm[n0 + tx * TN];
        float en[TN] = {en4.x, en4.y, en4.z, en4.w};
#pragma unroll
        for (int i = 0; i < TM; ++i) {
            float bs = en[0] - 2.f * acc[i][0];
            int   bj = 0;
#pragma unroll
            for (int j = 1; j < TN; ++j) {
                float s = en[j] - 2.f * acc[i][j];
                if (s < bs) { bs = s; bj = j; }     // strict < : first index wins
            }
            unsigned u = __float_as_uint(bs);
            u = (u & 0x80000000u) ? ~u : (u | 0x80000000u);   // order-preserving map
            unsigned long long p =
                ((unsigned long long)u << 32) | (unsigned)(n0 + tx * TN + bj);
            // warp reduce min (all lanes of this warp share row ty*TM+i)
#pragma unroll
            for (int off = 16; off; off >>= 1) {
                unsigned long long q = __shfl_xor_sync(0xffffffffu, p, off);
                p = (q < p) ? q : p;
            }
            if (tx == 0) atomicMin(&best[ty * TM + i], p);
        }
    }
    __syncthreads();

    // gather + loss (loss = 1.25 * mean((e[idx]-x)^2); STE output == e[idx])
    double lsum = 0.0;
    const int C4 = DIM / 4;                         // 128 float4 per row
    for (int i = tid; i < BM * C4; i += THREADS) {
        int r = i >> 7;
        int c = i & (C4 - 1);
        unsigned idx = (unsigned)best[r];           // low 32 bits = argmin index
        float4 e = *(const float4*)(ew + (size_t)idx * DIM + c * 4);
        float4 x = *(const float4*)(xs + (size_t)(rowBase + r) * DIM + c * 4);
        *(float4*)(out + (size_t)(rowBase + r) * DIM + c * 4) = e;
        float dx = e.x - x.x, dy = e.y - x.y, dz = e.z - x.z, dw = e.w - x.w;
        lsum += (double)(dx * dx + dy * dy) + (double)(dz * dz + dw * dw);
    }
#pragma unroll
    for (int off = 16; off; off >>= 1)
        lsum += __shfl_xor_sync(0xffffffffu, lsum, off);
    if (tx == 0) red[ty] = lsum;
    __syncthreads();
    if (ty == 0) {
        double v = (tx < THREADS / 32) ? red[tx] : 0.0;
#pragma unroll
        for (int off = 16; off; off >>= 1)
            v += __shfl_xor_sync(0xffffffffu, v, off);
        if (tx == 0) atomicAdd(&g_loss_sum, v);
    }
}

// ---------------------------------------------------------------------------
// finalize: write scalar loss
// ---------------------------------------------------------------------------
__global__ void vq_finalize_kernel(float* __restrict__ out,
                                   long long n_elems, long long pos) {
    out[pos] = (float)(1.25 * g_loss_sum / (double)n_elems);
}

extern "C" void kernel_launch(void* const* d_in, const int* in_sizes, int n_in,
                              void* d_out, int out_size) {
    const float* xs = (const float*)d_in[0];   // [N, 512]
    const float* ew = (const float*)d_in[1];   // [K, 512]
    float* out = (float*)d_out;                // [N, 512] output_x, then loss scalar

    int N = in_sizes[0] / DIM;
    int K = in_sizes[1] / DIM;

    int prepBlocks = (K * 32 + 255) / 256;     // one warp per codebook row
    vq_prep_kernel<<<prepBlocks, 256>>>(ew, K);
    vq_main_kernel<<<N / BM, THREADS>>>(xs, ew, out, K);

    long long nd = (long long)N * DIM;
    if ((long long)out_size > nd) {
        vq_finalize_kernel<<<1, 1>>>(out, nd, nd);
        if ((long long)out_size - 1 != nd)
            vq_finalize_kernel<<<1, 1>>>(out, nd, (long long)out_size - 1);
    }
}

// round 6
// speedup vs baseline: 1.9071x; 1.9071x over previous
#include <cuda_runtime.h>
#include <cuda_bf16.h>
#include <cstdint>

#define D_DIM 512
#define N_TOK 16384
#define K_MAX 8192
#define BM 128
#define BN 128
#define BK 64
#define THREADS_MAIN 256
#define STAGE_BYTES 65536
#define A_HI 0
#define A_LO 16384
#define B_HI 32768
#define B_LO 49152
#define DSMEM_BYTES (2 * STAGE_BYTES + 1024)
#define EPS_GAP 0.05f

// ------------------------- device-global scratch ---------------------------
__device__ __align__(256) __nv_bfloat16 g_xh[N_TOK * D_DIM];
__device__ __align__(256) __nv_bfloat16 g_xl[N_TOK * D_DIM];
__device__ __align__(256) __nv_bfloat16 g_eh[K_MAX * D_DIM];
__device__ __align__(256) __nv_bfloat16 g_el[K_MAX * D_DIM];
__device__ float  g_enorm[K_MAX];
__device__ int    g_bestidx[N_TOK];
__device__ int    g_unc_rows[N_TOK];
__device__ int    g_unc_count;
__device__ double g_loss_sum;

// ------------------------------ helpers ------------------------------------
__device__ __forceinline__ uint32_t smem_u32(const void* p) {
    uint32_t a;
    asm("{ .reg .u64 t; cvta.to.shared.u64 t, %1; cvt.u32.u64 %0, t; }"
        : "=r"(a) : "l"(p));
    return a;
}
__device__ __forceinline__ void cp_async16(uint32_t dst, const void* src) {
    asm volatile("cp.async.cg.shared.global [%0], [%1], 16;"
                 :: "r"(dst), "l"(src) : "memory");
}
__device__ __forceinline__ void ldsm4(uint32_t* r, uint32_t addr) {
    asm volatile("ldmatrix.sync.aligned.m8n8.x4.shared.b16 {%0,%1,%2,%3}, [%4];"
                 : "=r"(r[0]), "=r"(r[1]), "=r"(r[2]), "=r"(r[3]) : "r"(addr));
}
__device__ __forceinline__ void hmma(float* c, const uint32_t* a,
                                     uint32_t b0, uint32_t b1) {
    asm volatile(
        "mma.sync.aligned.m16n8k16.row.col.f32.bf16.bf16.f32 "
        "{%0,%1,%2,%3}, {%4,%5,%6,%7}, {%8,%9}, {%0,%1,%2,%3};"
        : "+f"(c[0]), "+f"(c[1]), "+f"(c[2]), "+f"(c[3])
        : "r"(a[0]), "r"(a[1]), "r"(a[2]), "r"(a[3]), "r"(b0), "r"(b1));
}
__device__ __forceinline__ unsigned ordf(float f) {
    unsigned u = __float_as_uint(f);
    return (u & 0x80000000u) ? ~u : (u | 0x80000000u);
}
__device__ __forceinline__ float unordf(unsigned u) {
    unsigned v = (u & 0x80000000u) ? (u & 0x7fffffffu) : ~u;
    return __uint_as_float(v);
}

// --------------------------- convert: fp32 -> bf16 hi/lo -------------------
__global__ void vq_convert_kernel(const float* __restrict__ xs,
                                  const float* __restrict__ ew,
                                  int nx2, int ne2) {
    int stride = gridDim.x * blockDim.x;
    for (int i = blockIdx.x * blockDim.x + threadIdx.x; i < nx2; i += stride) {
        float2 v = ((const float2*)xs)[i];
        __nv_bfloat16 hx = __float2bfloat16(v.x), hy = __float2bfloat16(v.y);
        ((__nv_bfloat162*)g_xh)[i] = __halves2bfloat162(hx, hy);
        ((__nv_bfloat162*)g_xl)[i] = __halves2bfloat162(
            __float2bfloat16(v.x - __bfloat162float(hx)),
            __float2bfloat16(v.y - __bfloat162float(hy)));
    }
    for (int i = blockIdx.x * blockDim.x + threadIdx.x; i < ne2; i += stride) {
        float2 v = ((const float2*)ew)[i];
        __nv_bfloat16 hx = __float2bfloat16(v.x), hy = __float2bfloat16(v.y);
        ((__nv_bfloat162*)g_eh)[i] = __halves2bfloat162(hx, hy);
        ((__nv_bfloat162*)g_el)[i] = __halves2bfloat162(
            __float2bfloat16(v.x - __bfloat162float(hx)),
            __float2bfloat16(v.y - __bfloat162float(hy)));
    }
}

// --------------------------- prep: enorm + zero scratch --------------------
__global__ void vq_prep_kernel(const float* __restrict__ ew, int K) {
    if (blockIdx.x == 0 && threadIdx.x == 0) { g_loss_sum = 0.0; g_unc_count = 0; }
    int warp = (blockIdx.x * blockDim.x + threadIdx.x) >> 5;
    int lane = threadIdx.x & 31;
    if (warp >= K) return;
    const float4* row = (const float4*)(ew + (size_t)warp * D_DIM);
    float s = 0.f;
#pragma unroll
    for (int it = 0; it < D_DIM / 128; ++it) {
        float4 v = row[lane + 32 * it];
        s += v.x * v.x + v.y * v.y + v.z * v.z + v.w * v.w;
    }
#pragma unroll
    for (int off = 16; off; off >>= 1) s += __shfl_xor_sync(0xffffffffu, s, off);
    if (lane == 0) g_enorm[warp] = s;
}

// --------------------------- chunk loader ----------------------------------
__device__ __forceinline__ void issue_chunk(uint32_t smBase, int g, int tid,
                                            int rowBase) {
    const int t = g >> 3, kc = g & 7;
    const int d0 = kc * BK, n0 = t * BN;
    const uint32_t st = smBase + (uint32_t)(g & 1) * STAGE_BYTES;
#pragma unroll
    for (int j = 0; j < 8; ++j) {
        int id = tid + THREADS_MAIN * j;
        int split = id >> 10, rem = id & 1023;
        int row = rem >> 3, seg = rem & 7;
        const __nv_bfloat16* src =
            (split ? g_xl : g_xh) + (size_t)(rowBase + row) * D_DIM + d0 + seg * 8;
        uint32_t off = (uint32_t)(row * 128) + ((uint32_t)(seg * 16) ^ ((row & 7) * 16));
        cp_async16(st + (split ? A_LO : A_HI) + off, src);
    }
#pragma unroll
    for (int j = 0; j < 8; ++j) {
        int id = tid + THREADS_MAIN * j;
        int split = id >> 10, rem = id & 1023;
        int row = rem >> 3, seg = rem & 7;
        const __nv_bfloat16* src =
            (split ? g_el : g_eh) + (size_t)(n0 + row) * D_DIM + d0 + seg * 8;
        uint32_t off = (uint32_t)(row * 128) + ((uint32_t)(seg * 16) ^ ((row & 7) * 16));
        cp_async16(st + (split ? B_LO : B_HI) + off, src);
    }
}

// --------------------------- main HMMA kernel ------------------------------
__global__ __launch_bounds__(THREADS_MAIN, 1)
void vq_hmma_kernel(int K) {
    extern __shared__ __align__(1024) char dsm_raw[];
    __shared__ unsigned long long best1[BM];
    __shared__ unsigned int       best2[BM];

    const int tid  = threadIdx.x;
    const int lane = tid & 31;
    const int warp = tid >> 5;
    const int wm   = warp >> 1;          // 0..3  (M warps, 32 rows each)
    const int wn   = warp & 1;           // 0..1  (N warps, 64 cols each)
    const int rowBase = blockIdx.x * BM;
    const uint32_t smBase = (smem_u32(dsm_raw) + 1023u) & ~1023u;

    for (int i = tid; i < BM; i += THREADS_MAIN) {
        best1[i] = ~0ull;
        best2[i] = 0xffffffffu;
    }

    float acc[2][8][4];
#pragma unroll
    for (int mf = 0; mf < 2; ++mf)
#pragma unroll
        for (int nf = 0; nf < 8; ++nf)
#pragma unroll
            for (int c = 0; c < 4; ++c) acc[mf][nf][c] = 0.f;

    float m1[4], m2[4];
    int   k1[4];
#pragma unroll
    for (int s = 0; s < 4; ++s) {
        m1[s] = __int_as_float(0x7f800000);
        m2[s] = __int_as_float(0x7f800000);
        k1[s] = 0;
    }

    // per-lane ldmatrix address components
    const uint32_t aRow0  = wm * 32 + (lane & 15);
    const uint32_t aKhalf = (lane & 16) ? 16u : 0u;
    const uint32_t bRow0  = wn * 64 + (lane & 7) + ((lane & 16) >> 1);
    const uint32_t bKhalf = (lane & 8) ? 16u : 0u;

    const int G = (K / BN) * 8;

    issue_chunk(smBase, 0, tid, rowBase);
    asm volatile("cp.async.commit_group;" ::: "memory");

    for (int g = 0; g < G; ++g) {
        if (g + 1 < G) {
            issue_chunk(smBase, g + 1, tid, rowBase);
            asm volatile("cp.async.commit_group;" ::: "memory");
            asm volatile("cp.async.wait_group 1;" ::: "memory");
        } else {
            asm volatile("cp.async.wait_group 0;" ::: "memory");
        }
        __syncthreads();

        const uint32_t st = smBase + (uint32_t)(g & 1) * STAGE_BYTES;
#pragma unroll
        for (int ks = 0; ks < 4; ++ks) {
            uint32_t ah[2][4], al[2][4], bh[4][4], bl[4][4];
#pragma unroll
            for (int mf = 0; mf < 2; ++mf) {
                uint32_t r    = aRow0 + mf * 16;
                uint32_t koff = (uint32_t)(ks * 32) + aKhalf;
                uint32_t addr = r * 128 + (koff ^ ((r & 7) * 16));
                ldsm4(ah[mf], st + A_HI + addr);
                ldsm4(al[mf], st + A_LO + addr);
            }
#pragma unroll
            for (int np = 0; np < 4; ++np) {
                uint32_t r    = bRow0 + np * 16;
                uint32_t koff = (uint32_t)(ks * 32) + bKhalf;
                uint32_t addr = r * 128 + (koff ^ ((r & 7) * 16));
                ldsm4(bh[np], st + B_HI + addr);
                ldsm4(bl[np], st + B_LO + addr);
            }
#pragma unroll
            for (int mf = 0; mf < 2; ++mf)
#pragma unroll
                for (int nf = 0; nf < 8; ++nf) {
                    uint32_t b0h = bh[nf >> 1][(nf & 1) * 2];
                    uint32_t b1h = bh[nf >> 1][(nf & 1) * 2 + 1];
                    uint32_t b0l = bl[nf >> 1][(nf & 1) * 2];
                    uint32_t b1l = bl[nf >> 1][(nf & 1) * 2 + 1];
                    hmma(acc[mf][nf], ah[mf], b0h, b1h);   // xh . eh
                    hmma(acc[mf][nf], ah[mf], b0l, b1l);   // xh . el
                    hmma(acc[mf][nf], al[mf], b0h, b1h);   // xl . eh
                }
        }

        if ((g & 7) == 7) {
            // tile epilogue: fold scores into per-thread running min1/min2
            const int n0 = (g >> 3) * BN;
#pragma unroll
            for (int nf = 0; nf < 8; ++nf) {
                int colb = n0 + wn * 64 + nf * 8 + 2 * (lane & 3);
                float en0 = g_enorm[colb];
                float en1 = g_enorm[colb + 1];
#pragma unroll
                for (int mf = 0; mf < 2; ++mf)
#pragma unroll
                    for (int h = 0; h < 2; ++h) {
                        int s = mf * 2 + h;
                        float sc0 = fmaf(-2.f, acc[mf][nf][2 * h], en0);
                        float sc1 = fmaf(-2.f, acc[mf][nf][2 * h + 1], en1);
                        if (sc0 < m1[s]) { m2[s] = m1[s]; m1[s] = sc0; k1[s] = colb; }
                        else if (sc0 < m2[s]) m2[s] = sc0;
                        if (sc1 < m1[s]) { m2[s] = m1[s]; m1[s] = sc1; k1[s] = colb + 1; }
                        else if (sc1 < m2[s]) m2[s] = sc1;
                        acc[mf][nf][2 * h]     = 0.f;
                        acc[mf][nf][2 * h + 1] = 0.f;
                    }
            }
        }
        __syncthreads();
    }

    // ---- final cross-thread merge (exact min1 / min2 per row) -------------
    unsigned long long pk[4];
#pragma unroll
    for (int s = 0; s < 4; ++s) {
        int r = wm * 32 + (s >> 1) * 16 + (s & 1) * 8 + (lane >> 2);
        pk[s] = ((unsigned long long)ordf(m1[s]) << 32) | (unsigned)k1[s];
        atomicMin(&best1[r], pk[s]);
    }
    __syncthreads();
#pragma unroll
    for (int s = 0; s < 4; ++s) {
        int r = wm * 32 + (s >> 1) * 16 + (s & 1) * 8 + (lane >> 2);
        unsigned cand = (pk[s] == best1[r]) ? ordf(m2[s]) : ordf(m1[s]);
        atomicMin(&best2[r], cand);
    }
    __syncthreads();
    if (tid < BM) {
        int row = rowBase + tid;
        unsigned long long w = best1[tid];
        g_bestidx[row] = (int)(unsigned)w;
        float bm1 = unordf((unsigned)(w >> 32));
        float bm2 = unordf(best2[tid]);
        if (bm2 - bm1 < EPS_GAP) {
            int p = atomicAdd(&g_unc_count, 1);
            g_unc_rows[p] = row;
        }
    }
}

// ------------------- cleanup: exact fp32 rescore of flagged rows -----------
__global__ __launch_bounds__(256)
void vq_cleanup_kernel(const float* __restrict__ xs,
                       const float* __restrict__ ew, int K) {
    __shared__ float xrow[D_DIM];
    __shared__ unsigned long long red[8];
    int cnt = *(volatile int*)&g_unc_count;
    for (int u = blockIdx.x; u < cnt; u += gridDim.x) {
        int row = g_unc_rows[u];
        for (int i = threadIdx.x; i < D_DIM; i += 256)
            xrow[i] = xs[(size_t)row * D_DIM + i];
        __syncthreads();
        unsigned long long best = ~0ull;
        for (int k = threadIdx.x; k < K; k += 256) {
            const float4* er = (const float4*)(ew + (size_t)k * D_DIM);
            float dot = 0.f;
#pragma unroll
            for (int d = 0; d < D_DIM / 4; ++d) {
                float4 e = er[d];
                const float4 x = *(const float4*)&xrow[d * 4];
                dot = fmaf(e.x, x.x, fmaf(e.y, x.y, fmaf(e.z, x.z, fmaf(e.w, x.w, dot))));
            }
            float sc = g_enorm[k] - 2.f * dot;
            unsigned long long p = ((unsigned long long)ordf(sc) << 32) | (unsigned)k;
            if (p < best) best = p;
        }
#pragma unroll
        for (int off = 16; off; off >>= 1) {
            unsigned long long q = __shfl_xor_sync(0xffffffffu, best, off);
            if (q < best) best = q;
        }
        if ((threadIdx.x & 31) == 0) red[threadIdx.x >> 5] = best;
        __syncthreads();
        if (threadIdx.x < 32) {
            unsigned long long v = (threadIdx.x < 8) ? red[threadIdx.x] : ~0ull;
#pragma unroll
            for (int off = 4; off; off >>= 1) {
                unsigned long long q = __shfl_xor_sync(0xffffffffu, v, off);
                if (q < v) v = q;
            }
            if (threadIdx.x == 0) g_bestidx[row] = (int)(unsigned)v;
        }
        __syncthreads();
    }
}

// ----------------------- gather + loss ------------------------------------
__global__ __launch_bounds__(256)
void vq_gather_kernel(const float* __restrict__ xs,
                      const float* __restrict__ ew,
                      float* __restrict__ out) {
    __shared__ double red[8];
    double lsum = 0.0;
    int base = blockIdx.x * 32;
    for (int j = threadIdx.x; j < 32 * 128; j += 256) {
        int r = base + (j >> 7);
        int c = j & 127;
        int idx = g_bestidx[r];
        float4 e = *(const float4*)(ew + (size_t)idx * D_DIM + c * 4);
        float4 x = *(const float4*)(xs + (size_t)r * D_DIM + c * 4);
        *(float4*)(out + (size_t)r * D_DIM + c * 4) = e;
        float dx = e.x - x.x, dy = e.y - x.y, dz = e.z - x.z, dw = e.w - x.w;
        lsum += (double)(dx * dx + dy * dy) + (double)(dz * dz + dw * dw);
    }
#pragma unroll
    for (int off = 16; off; off >>= 1) lsum += __shfl_xor_sync(0xffffffffu, lsum, off);
    if ((threadIdx.x & 31) == 0) red[threadIdx.x >> 5] = lsum;
    __syncthreads();
    if (threadIdx.x < 32) {
        double v = (threadIdx.x < 8) ? red[threadIdx.x] : 0.0;
#pragma unroll
        for (int off = 4; off; off >>= 1) v += __shfl_xor_sync(0xffffffffu, v, off);
        if (threadIdx.x == 0) atomicAdd(&g_loss_sum, v);
    }
}

__global__ void vq_finalize_kernel(float* __restrict__ out,
                                   long long n_elems, long long pos) {
    out[pos] = (float)(1.25 * g_loss_sum / (double)n_elems);
}

// ------------------------------ launch -------------------------------------
extern "C" void kernel_launch(void* const* d_in, const int* in_sizes, int n_in,
                              void* d_out, int out_size) {
    const float* xs = (const float*)d_in[0];   // [N, 512]
    const float* ew = (const float*)d_in[1];   // [K, 512]
    float* out = (float*)d_out;

    int N = in_sizes[0] / D_DIM;
    int K = in_sizes[1] / D_DIM;

    cudaFuncSetAttribute(vq_hmma_kernel,
                         cudaFuncAttributeMaxDynamicSharedMemorySize, DSMEM_BYTES);

    vq_convert_kernel<<<4096, 256>>>(xs, ew, N * D_DIM / 2, K * D_DIM / 2);
    vq_prep_kernel<<<(K * 32 + 255) / 256, 256>>>(ew, K);
    vq_hmma_kernel<<<N / BM, THREADS_MAIN, DSMEM_BYTES>>>(K);
    vq_cleanup_kernel<<<128, 256>>>(xs, ew, K);
    vq_gather_kernel<<<N / 32, 256>>>(xs, ew, out);

    long long nd = (long long)N * D_DIM;
    if ((long long)out_size > nd) {
        vq_finalize_kernel<<<1, 1>>>(out, nd, nd);
        if ((long long)out_size - 1 != nd)
            vq_finalize_kernel<<<1, 1>>>(out, nd, (long long)out_size - 1);
    }
}

// round 7
// speedup vs baseline: 2.7957x; 1.4659x over previous
#include <cuda_runtime.h>
#include <cuda_fp16.h>
#include <cstdint>

#define D_DIM 512
#define N_TOK 16384
#define K_MAX 8192
#define BM 128
#define BN 128
#define BK 64
#define THREADS_MAIN 256
#define STAGE_BYTES 49152
#define A_HI 0
#define B_HI 16384
#define B_LO 32768
#define DSMEM_BYTES (2 * STAGE_BYTES + 1024)
#define EPS_GAP 0.08f

// ------------------------- device-global scratch ---------------------------
__device__ __align__(256) __half g_xh[N_TOK * D_DIM];
__device__ __align__(256) __half g_eh[K_MAX * D_DIM];
__device__ __align__(256) __half g_el[K_MAX * D_DIM];
__device__ float  g_enorm[K_MAX];
__device__ int    g_bestidx[N_TOK];
__device__ int    g_unc_rows[N_TOK];
__device__ unsigned long long g_unc_best[N_TOK];
__device__ int    g_unc_count;
__device__ double g_loss_sum;

// ------------------------------ helpers ------------------------------------
__device__ __forceinline__ uint32_t smem_u32(const void* p) {
    uint32_t a;
    asm("{ .reg .u64 t; cvta.to.shared.u64 t, %1; cvt.u32.u64 %0, t; }"
        : "=r"(a) : "l"(p));
    return a;
}
__device__ __forceinline__ void cp_async16(uint32_t dst, const void* src) {
    asm volatile("cp.async.cg.shared.global [%0], [%1], 16;"
                 :: "r"(dst), "l"(src) : "memory");
}
__device__ __forceinline__ void ldsm4(uint32_t* r, uint32_t addr) {
    asm volatile("ldmatrix.sync.aligned.m8n8.x4.shared.b16 {%0,%1,%2,%3}, [%4];"
                 : "=r"(r[0]), "=r"(r[1]), "=r"(r[2]), "=r"(r[3]) : "r"(addr));
}
__device__ __forceinline__ void hmma(float* c, const uint32_t* a,
                                     uint32_t b0, uint32_t b1) {
    asm volatile(
        "mma.sync.aligned.m16n8k16.row.col.f32.f16.f16.f32 "
        "{%0,%1,%2,%3}, {%4,%5,%6,%7}, {%8,%9}, {%0,%1,%2,%3};"
        : "+f"(c[0]), "+f"(c[1]), "+f"(c[2]), "+f"(c[3])
        : "r"(a[0]), "r"(a[1]), "r"(a[2]), "r"(a[3]), "r"(b0), "r"(b1));
}
__device__ __forceinline__ unsigned ordf(float f) {
    unsigned u = __float_as_uint(f);
    return (u & 0x80000000u) ? ~u : (u | 0x80000000u);
}
__device__ __forceinline__ float unordf(unsigned u) {
    unsigned v = (u & 0x80000000u) ? (u & 0x7fffffffu) : ~u;
    return __uint_as_float(v);
}

// --------------------------- convert: fp32 -> fp16 (x hi; e hi/lo) ---------
__global__ void vq_convert_kernel(const float* __restrict__ xs,
                                  const float* __restrict__ ew,
                                  int nx2, int ne2) {
    int stride = gridDim.x * blockDim.x;
    for (int i = blockIdx.x * blockDim.x + threadIdx.x; i < nx2; i += stride) {
        float2 v = ((const float2*)xs)[i];
        ((__half2*)g_xh)[i] = __floats2half2_rn(v.x, v.y);
    }
    for (int i = blockIdx.x * blockDim.x + threadIdx.x; i < ne2; i += stride) {
        float2 v = ((const float2*)ew)[i];
        __half hx = __float2half_rn(v.x), hy = __float2half_rn(v.y);
        ((__half2*)g_eh)[i] = __halves2half2(hx, hy);
        ((__half2*)g_el)[i] = __halves2half2(
            __float2half_rn(v.x - __half2float(hx)),
            __float2half_rn(v.y - __half2float(hy)));
    }
}

// --------------------------- prep: enorm + zero scratch --------------------
__global__ void vq_prep_kernel(const float* __restrict__ ew, int K) {
    if (blockIdx.x == 0 && threadIdx.x == 0) { g_loss_sum = 0.0; g_unc_count = 0; }
    int warp = (blockIdx.x * blockDim.x + threadIdx.x) >> 5;
    int lane = threadIdx.x & 31;
    if (warp >= K) return;
    const float4* row = (const float4*)(ew + (size_t)warp * D_DIM);
    float s = 0.f;
#pragma unroll
    for (int it = 0; it < D_DIM / 128; ++it) {
        float4 v = row[lane + 32 * it];
        s += v.x * v.x + v.y * v.y + v.z * v.z + v.w * v.w;
    }
#pragma unroll
    for (int off = 16; off; off >>= 1) s += __shfl_xor_sync(0xffffffffu, s, off);
    if (lane == 0) g_enorm[warp] = s;
}

// --------------------------- chunk loader ----------------------------------
__device__ __forceinline__ void issue_chunk(uint32_t smBase, int g, int tid,
                                            int rowBase) {
    const int t = g >> 3, kc = g & 7;
    const int d0 = kc * BK, n0 = t * BN;
    const uint32_t st = smBase + (uint32_t)(g & 1) * STAGE_BYTES;
    // A hi: 128 rows x 64 fp16 = 1024 x 16B
#pragma unroll
    for (int j = 0; j < 4; ++j) {
        int id  = tid + THREADS_MAIN * j;
        int row = id >> 3, seg = id & 7;
        const __half* src = g_xh + (size_t)(rowBase + row) * D_DIM + d0 + seg * 8;
        uint32_t off = (uint32_t)(row * 128) + ((uint32_t)(seg * 16) ^ ((row & 7) * 16));
        cp_async16(st + A_HI + off, src);
    }
    // B hi + lo: 2 x 128 rows x 64 fp16
#pragma unroll
    for (int j = 0; j < 8; ++j) {
        int id    = tid + THREADS_MAIN * j;
        int split = id >> 10, rem = id & 1023;
        int row = rem >> 3, seg = rem & 7;
        const __half* src =
            (split ? g_el : g_eh) + (size_t)(n0 + row) * D_DIM + d0 + seg * 8;
        uint32_t off = (uint32_t)(row * 128) + ((uint32_t)(seg * 16) ^ ((row & 7) * 16));
        cp_async16(st + (split ? B_LO : B_HI) + off, src);
    }
}

// --------------------------- main HMMA kernel ------------------------------
__global__ __launch_bounds__(THREADS_MAIN, 1)
void vq_hmma_kernel(int K) {
    extern __shared__ __align__(1024) char dsm_raw[];
    __shared__ unsigned long long best1[BM];
    __shared__ unsigned int       best2[BM];

    const int tid  = threadIdx.x;
    const int lane = tid & 31;
    const int warp = tid >> 5;
    const int wm   = warp >> 1;
    const int wn   = warp & 1;
    const int rowBase = blockIdx.x * BM;
    const uint32_t smBase = (smem_u32(dsm_raw) + 1023u) & ~1023u;

    for (int i = tid; i < BM; i += THREADS_MAIN) {
        best1[i] = ~0ull;
        best2[i] = 0xffffffffu;
    }

    float acc[2][8][4];
#pragma unroll
    for (int mf = 0; mf < 2; ++mf)
#pragma unroll
        for (int nf = 0; nf < 8; ++nf)
#pragma unroll
            for (int c = 0; c < 4; ++c) acc[mf][nf][c] = 0.f;

    float m1[4], m2[4];
    int   k1[4];
#pragma unroll
    for (int s = 0; s < 4; ++s) {
        m1[s] = __int_as_float(0x7f800000);
        m2[s] = __int_as_float(0x7f800000);
        k1[s] = 0;
    }

    const uint32_t aRow0  = wm * 32 + (lane & 15);
    const uint32_t aKhalf = (lane & 16) ? 16u : 0u;
    const uint32_t bRow0  = wn * 64 + (lane & 7) + ((lane & 16) >> 1);
    const uint32_t bKhalf = (lane & 8) ? 16u : 0u;

    const int G = (K / BN) * 8;

    issue_chunk(smBase, 0, tid, rowBase);
    asm volatile("cp.async.commit_group;" ::: "memory");

    for (int g = 0; g < G; ++g) {
        if (g + 1 < G) {
            issue_chunk(smBase, g + 1, tid, rowBase);
            asm volatile("cp.async.commit_group;" ::: "memory");
            asm volatile("cp.async.wait_group 1;" ::: "memory");
        } else {
            asm volatile("cp.async.wait_group 0;" ::: "memory");
        }
        __syncthreads();

        const uint32_t st = smBase + (uint32_t)(g & 1) * STAGE_BYTES;
#pragma unroll
        for (int ks = 0; ks < 4; ++ks) {
            uint32_t ah[2][4], bh[4][4], bl[4][4];
#pragma unroll
            for (int mf = 0; mf < 2; ++mf) {
                uint32_t r    = aRow0 + mf * 16;
                uint32_t koff = (uint32_t)(ks * 32) + aKhalf;
                uint32_t addr = r * 128 + (koff ^ ((r & 7) * 16));
                ldsm4(ah[mf], st + A_HI + addr);
            }
#pragma unroll
            for (int np = 0; np < 4; ++np) {
                uint32_t r    = bRow0 + np * 16;
                uint32_t koff = (uint32_t)(ks * 32) + bKhalf;
                uint32_t addr = r * 128 + (koff ^ ((r & 7) * 16));
                ldsm4(bh[np], st + B_HI + addr);
                ldsm4(bl[np], st + B_LO + addr);
            }
#pragma unroll
            for (int mf = 0; mf < 2; ++mf)
#pragma unroll
                for (int nf = 0; nf < 8; ++nf) {
                    uint32_t b0h = bh[nf >> 1][(nf & 1) * 2];
                    uint32_t b1h = bh[nf >> 1][(nf & 1) * 2 + 1];
                    uint32_t b0l = bl[nf >> 1][(nf & 1) * 2];
                    uint32_t b1l = bl[nf >> 1][(nf & 1) * 2 + 1];
                    hmma(acc[mf][nf], ah[mf], b0h, b1h);   // xh . eh
                    hmma(acc[mf][nf], ah[mf], b0l, b1l);   // xh . el
                }
        }

        if ((g & 7) == 7) {
            const int n0 = (g >> 3) * BN;
#pragma unroll
            for (int nf = 0; nf < 8; ++nf) {
                int colb = n0 + wn * 64 + nf * 8 + 2 * (lane & 3);
                float en0 = g_enorm[colb];
                float en1 = g_enorm[colb + 1];
#pragma unroll
                for (int mf = 0; mf < 2; ++mf)
#pragma unroll
                    for (int h = 0; h < 2; ++h) {
                        int s = mf * 2 + h;
                        float sc0 = fmaf(-2.f, acc[mf][nf][2 * h], en0);
                        float sc1 = fmaf(-2.f, acc[mf][nf][2 * h + 1], en1);
                        if (sc0 < m1[s]) { m2[s] = m1[s]; m1[s] = sc0; k1[s] = colb; }
                        else if (sc0 < m2[s]) m2[s] = sc0;
                        if (sc1 < m1[s]) { m2[s] = m1[s]; m1[s] = sc1; k1[s] = colb + 1; }
                        else if (sc1 < m2[s]) m2[s] = sc1;
                        acc[mf][nf][2 * h]     = 0.f;
                        acc[mf][nf][2 * h + 1] = 0.f;
                    }
            }
        }
        __syncthreads();
    }

    // ---- final cross-thread merge -----------------------------------------
    unsigned long long pk[4];
#pragma unroll
    for (int s = 0; s < 4; ++s) {
        int r = wm * 32 + (s >> 1) * 16 + (s & 1) * 8 + (lane >> 2);
        pk[s] = ((unsigned long long)ordf(m1[s]) << 32) | (unsigned)k1[s];
        atomicMin(&best1[r], pk[s]);
    }
    __syncthreads();
#pragma unroll
    for (int s = 0; s < 4; ++s) {
        int r = wm * 32 + (s >> 1) * 16 + (s & 1) * 8 + (lane >> 2);
        unsigned cand = (pk[s] == best1[r]) ? ordf(m2[s]) : ordf(m1[s]);
        atomicMin(&best2[r], cand);
    }
    __syncthreads();
    if (tid < BM) {
        int row = rowBase + tid;
        unsigned long long w = best1[tid];
        g_bestidx[row] = (int)(unsigned)w;
        float bm1 = unordf((unsigned)(w >> 32));
        float bm2 = unordf(best2[tid]);
        if (bm2 - bm1 < EPS_GAP) {
            int p = atomicAdd(&g_unc_count, 1);
            g_unc_rows[p] = row;
            g_unc_best[p] = ~0ull;
        }
    }
}

// ---------- cleanup: exact fp32 rescore, (row, slice) parallel -------------
__global__ __launch_bounds__(256)
void vq_cleanup_kernel(const float* __restrict__ xs,
                       const float* __restrict__ ew, int K) {
    __shared__ float xrow[D_DIM];
    __shared__ unsigned long long red[8];
    const int slices = K >> 9;                 // 512 codes per slice
    int cnt = *(volatile int*)&g_unc_count;
    int tasks = cnt * slices;
    for (int t = blockIdx.x; t < tasks; t += gridDim.x) {
        int u  = t / slices;
        int sl = t - u * slices;
        int row = g_unc_rows[u];
        __syncthreads();
        for (int i = threadIdx.x; i < D_DIM; i += 256)
            xrow[i] = xs[(size_t)row * D_DIM + i];
        __syncthreads();
        unsigned long long best = ~0ull;
#pragma unroll
        for (int kk = 0; kk < 2; ++kk) {
            int k = sl * 512 + kk * 256 + threadIdx.x;
            const float4* er = (const float4*)(ew + (size_t)k * D_DIM);
            const float4* xr = (const float4*)xrow;
            float a0 = 0.f, a1 = 0.f, a2 = 0.f, a3 = 0.f;
#pragma unroll 4
            for (int d = 0; d < D_DIM / 4; d += 4) {
                float4 e0 = er[d],     x0 = xr[d];
                float4 e1 = er[d + 1], x1 = xr[d + 1];
                float4 e2 = er[d + 2], x2 = xr[d + 2];
                float4 e3 = er[d + 3], x3 = xr[d + 3];
                a0 = fmaf(e0.x, x0.x, fmaf(e0.y, x0.y, fmaf(e0.z, x0.z, fmaf(e0.w, x0.w, a0))));
                a1 = fmaf(e1.x, x1.x, fmaf(e1.y, x1.y, fmaf(e1.z, x1.z, fmaf(e1.w, x1.w, a1))));
                a2 = fmaf(e2.x, x2.x, fmaf(e2.y, x2.y, fmaf(e2.z, x2.z, fmaf(e2.w, x2.w, a2))));
                a3 = fmaf(e3.x, x3.x, fmaf(e3.y, x3.y, fmaf(e3.z, x3.z, fmaf(e3.w, x3.w, a3))));
            }
            float dot = (a0 + a1) + (a2 + a3);
            float sc  = g_enorm[k] - 2.f * dot;
            unsigned long long p = ((unsigned long long)ordf(sc) << 32) | (unsigned)k;
            if (p < best) best = p;
        }
#pragma unroll
        for (int off = 16; off; off >>= 1) {
            unsigned long long q = __shfl_xor_sync(0xffffffffu, best, off);
            if (q < best) best = q;
        }
        if ((threadIdx.x & 31) == 0) red[threadIdx.x >> 5] = best;
        __syncthreads();
        if (threadIdx.x == 0) {
            unsigned long long v = red[0];
#pragma unroll
            for (int w = 1; w < 8; ++w) if (red[w] < v) v = red[w];
            atomicMin(&g_unc_best[u], v);
        }
    }
}

// --------------- apply: write resolved indices back ------------------------
__global__ void vq_apply_kernel() {
    int cnt = *(volatile int*)&g_unc_count;
    for (int i = blockIdx.x * blockDim.x + threadIdx.x; i < cnt;
         i += gridDim.x * blockDim.x)
        g_bestidx[g_unc_rows[i]] = (int)(unsigned)g_unc_best[i];
}

// ----------------------- gather + loss ------------------------------------
__global__ __launch_bounds__(256)
void vq_gather_kernel(const float* __restrict__ xs,
                      const float* __restrict__ ew,
                      float* __restrict__ out) {
    __shared__ double red[8];
    double lsum = 0.0;
    int base = blockIdx.x * 32;
    for (int j = threadIdx.x; j < 32 * 128; j += 256) {
        int r = base + (j >> 7);
        int c = j & 127;
        int idx = g_bestidx[r];
        float4 e = *(const float4*)(ew + (size_t)idx * D_DIM + c * 4);
        float4 x = *(const float4*)(xs + (size_t)r * D_DIM + c * 4);
        *(float4*)(out + (size_t)r * D_DIM + c * 4) = e;
        float dx = e.x - x.x, dy = e.y - x.y, dz = e.z - x.z, dw = e.w - x.w;
        lsum += (double)(dx * dx + dy * dy) + (double)(dz * dz + dw * dw);
    }
#pragma unroll
    for (int off = 16; off; off >>= 1) lsum += __shfl_xor_sync(0xffffffffu, lsum, off);
    if ((threadIdx.x & 31) == 0) red[threadIdx.x >> 5] = lsum;
    __syncthreads();
    if (threadIdx.x < 32) {
        double v = (threadIdx.x < 8) ? red[threadIdx.x] : 0.0;
#pragma unroll
        for (int off = 4; off; off >>= 1) v += __shfl_xor_sync(0xffffffffu, v, off);
        if (threadIdx.x == 0) atomicAdd(&g_loss_sum, v);
    }
}

__global__ void vq_finalize_kernel(float* __restrict__ out,
                                   long long n_elems, long long pos) {
    out[pos] = (float)(1.25 * g_loss_sum / (double)n_elems);
}

// ------------------------------ launch -------------------------------------
extern "C" void kernel_launch(void* const* d_in, const int* in_sizes, int n_in,
                              void* d_out, int out_size) {
    const float* xs = (const float*)d_in[0];   // [N, 512]
    const float* ew = (const float*)d_in[1];   // [K, 512]
    float* out = (float*)d_out;

    int N = in_sizes[0] / D_DIM;
    int K = in_sizes[1] / D_DIM;

    cudaFuncSetAttribute(vq_hmma_kernel,
                         cudaFuncAttributeMaxDynamicSharedMemorySize, DSMEM_BYTES);

    vq_convert_kernel<<<4096, 256>>>(xs, ew, N * D_DIM / 2, K * D_DIM / 2);
    vq_prep_kernel<<<(K * 32 + 255) / 256, 256>>>(ew, K);
    vq_hmma_kernel<<<N / BM, THREADS_MAIN, DSMEM_BYTES>>>(K);
    vq_cleanup_kernel<<<2048, 256>>>(xs, ew, K);
    vq_apply_kernel<<<16, 256>>>();
    vq_gather_kernel<<<N / 32, 256>>>(xs, ew, out);

    long long nd = (long long)N * D_DIM;
    if ((long long)out_size > nd) {
        vq_finalize_kernel<<<1, 1>>>(out, nd, nd);
        if ((long long)out_size - 1 != nd)
            vq_finalize_kernel<<<1, 1>>>(out, nd, (long long)out_size - 1);
    }
}

// round 8
// speedup vs baseline: 4.5161x; 1.6154x over previous
#include <cuda_runtime.h>
#include <cuda_fp16.h>
#include <cstdint>

#define D_DIM 512
#define N_TOK 16384
#define K_MAX 8192
#define BM 128
#define BN 128
#define BK 64
#define THREADS_MAIN 256
#define STAGES 3
#define STAGE_BYTES 32768
#define A_HI 0
#define B_HI 16384
#define DSMEM_BYTES (STAGES * STAGE_BYTES + 1024)
#define EPS_GAP 0.12f
#define CL_ROWS 16
#define CL_SLICE 256

// ------------------------- device-global scratch ---------------------------
__device__ __align__(256) __half g_xh[N_TOK * D_DIM];
__device__ __align__(256) __half g_eh[K_MAX * D_DIM];
__device__ float  g_enorm[K_MAX];
__device__ int    g_bestidx[N_TOK];
__device__ int    g_unc_rows[N_TOK];
__device__ unsigned long long g_unc_best[N_TOK];
__device__ int    g_unc_count;
__device__ double g_loss_sum;

// ------------------------------ helpers ------------------------------------
__device__ __forceinline__ uint32_t smem_u32(const void* p) {
    uint32_t a;
    asm("{ .reg .u64 t; cvta.to.shared.u64 t, %1; cvt.u32.u64 %0, t; }"
        : "=r"(a) : "l"(p));
    return a;
}
__device__ __forceinline__ void cp_async16(uint32_t dst, const void* src) {
    asm volatile("cp.async.cg.shared.global [%0], [%1], 16;"
                 :: "r"(dst), "l"(src) : "memory");
}
__device__ __forceinline__ void ldsm4(uint32_t* r, uint32_t addr) {
    asm volatile("ldmatrix.sync.aligned.m8n8.x4.shared.b16 {%0,%1,%2,%3}, [%4];"
                 : "=r"(r[0]), "=r"(r[1]), "=r"(r[2]), "=r"(r[3]) : "r"(addr));
}
__device__ __forceinline__ void hmma(float* c, const uint32_t* a,
                                     uint32_t b0, uint32_t b1) {
    asm volatile(
        "mma.sync.aligned.m16n8k16.row.col.f32.f16.f16.f32 "
        "{%0,%1,%2,%3}, {%4,%5,%6,%7}, {%8,%9}, {%0,%1,%2,%3};"
        : "+f"(c[0]), "+f"(c[1]), "+f"(c[2]), "+f"(c[3])
        : "r"(a[0]), "r"(a[1]), "r"(a[2]), "r"(a[3]), "r"(b0), "r"(b1));
}
__device__ __forceinline__ unsigned ordf(float f) {
    unsigned u = __float_as_uint(f);
    return (u & 0x80000000u) ? ~u : (u | 0x80000000u);
}
__device__ __forceinline__ float unordf(unsigned u) {
    unsigned v = (u & 0x80000000u) ? (u & 0x7fffffffu) : ~u;
    return __uint_as_float(v);
}

// --------------------------- convert: fp32 -> fp16 -------------------------
__global__ void vq_convert_kernel(const float* __restrict__ xs,
                                  const float* __restrict__ ew,
                                  int nx2, int ne2) {
    int stride = gridDim.x * blockDim.x;
    for (int i = blockIdx.x * blockDim.x + threadIdx.x; i < nx2; i += stride) {
        float2 v = ((const float2*)xs)[i];
        ((__half2*)g_xh)[i] = __floats2half2_rn(v.x, v.y);
    }
    for (int i = blockIdx.x * blockDim.x + threadIdx.x; i < ne2; i += stride) {
        float2 v = ((const float2*)ew)[i];
        ((__half2*)g_eh)[i] = __floats2half2_rn(v.x, v.y);
    }
}

// --------------------------- prep: enorm + zero scratch --------------------
__global__ void vq_prep_kernel(const float* __restrict__ ew, int K) {
    if (blockIdx.x == 0 && threadIdx.x == 0) { g_loss_sum = 0.0; g_unc_count = 0; }
    int warp = (blockIdx.x * blockDim.x + threadIdx.x) >> 5;
    int lane = threadIdx.x & 31;
    if (warp >= K) return;
    const float4* row = (const float4*)(ew + (size_t)warp * D_DIM);
    float s = 0.f;
#pragma unroll
    for (int it = 0; it < D_DIM / 128; ++it) {
        float4 v = row[lane + 32 * it];
        s += v.x * v.x + v.y * v.y + v.z * v.z + v.w * v.w;
    }
#pragma unroll
    for (int off = 16; off; off >>= 1) s += __shfl_xor_sync(0xffffffffu, s, off);
    if (lane == 0) g_enorm[warp] = s;
}

// --------------------------- chunk loader ----------------------------------
__device__ __forceinline__ void issue_chunk(uint32_t smBase, int g, int tid,
                                            int rowBase) {
    const int t = g >> 3, kc = g & 7;
    const int d0 = kc * BK, n0 = t * BN;
    const uint32_t st = smBase + (uint32_t)(g % STAGES) * STAGE_BYTES;
#pragma unroll
    for (int j = 0; j < 4; ++j) {
        int id  = tid + THREADS_MAIN * j;
        int row = id >> 3, seg = id & 7;
        const __half* src = g_xh + (size_t)(rowBase + row) * D_DIM + d0 + seg * 8;
        uint32_t off = (uint32_t)(row * 128) + ((uint32_t)(seg * 16) ^ ((row & 7) * 16));
        cp_async16(st + A_HI + off, src);
    }
#pragma unroll
    for (int j = 0; j < 4; ++j) {
        int id  = tid + THREADS_MAIN * j;
        int row = id >> 3, seg = id & 7;
        const __half* src = g_eh + (size_t)(n0 + row) * D_DIM + d0 + seg * 8;
        uint32_t off = (uint32_t)(row * 128) + ((uint32_t)(seg * 16) ^ ((row & 7) * 16));
        cp_async16(st + B_HI + off, src);
    }
}

// --------------------------- main HMMA kernel ------------------------------
__global__ __launch_bounds__(THREADS_MAIN, 1)
void vq_hmma_kernel(int K) {
    extern __shared__ __align__(1024) char dsm_raw[];
    __shared__ unsigned long long best1[BM];
    __shared__ unsigned int       best2[BM];

    const int tid  = threadIdx.x;
    const int lane = tid & 31;
    const int warp = tid >> 5;
    const int wm   = warp >> 1;
    const int wn   = warp & 1;
    const int rowBase = blockIdx.x * BM;
    const uint32_t smBase = (smem_u32(dsm_raw) + 1023u) & ~1023u;

    for (int i = tid; i < BM; i += THREADS_MAIN) {
        best1[i] = ~0ull;
        best2[i] = 0xffffffffu;
    }

    float acc[2][8][4];
#pragma unroll
    for (int mf = 0; mf < 2; ++mf)
#pragma unroll
        for (int nf = 0; nf < 8; ++nf)
#pragma unroll
            for (int c = 0; c < 4; ++c) acc[mf][nf][c] = 0.f;

    float m1[4], m2[4];
    int   k1[4];
#pragma unroll
    for (int s = 0; s < 4; ++s) {
        m1[s] = __int_as_float(0x7f800000);
        m2[s] = __int_as_float(0x7f800000);
        k1[s] = 0;
    }

    const uint32_t aRow0  = wm * 32 + (lane & 15);
    const uint32_t aKhalf = (lane & 16) ? 16u : 0u;
    const uint32_t bRow0  = wn * 64 + (lane & 7) + ((lane & 16) >> 1);
    const uint32_t bKhalf = (lane & 8) ? 16u : 0u;

    const int G = (K / BN) * 8;

    issue_chunk(smBase, 0, tid, rowBase);
    asm volatile("cp.async.commit_group;" ::: "memory");
    issue_chunk(smBase, 1, tid, rowBase);
    asm volatile("cp.async.commit_group;" ::: "memory");

    for (int g = 0; g < G; ++g) {
        if (g + 2 < G) {
            issue_chunk(smBase, g + 2, tid, rowBase);
            asm volatile("cp.async.commit_group;" ::: "memory");
            asm volatile("cp.async.wait_group 2;" ::: "memory");
        } else if (g + 1 < G) {
            asm volatile("cp.async.wait_group 1;" ::: "memory");
        } else {
            asm volatile("cp.async.wait_group 0;" ::: "memory");
        }
        __syncthreads();

        const uint32_t st = smBase + (uint32_t)(g % STAGES) * STAGE_BYTES;
#pragma unroll
        for (int ks = 0; ks < 4; ++ks) {
            uint32_t ah[2][4], bh[4][4];
#pragma unroll
            for (int mf = 0; mf < 2; ++mf) {
                uint32_t r    = aRow0 + mf * 16;
                uint32_t koff = (uint32_t)(ks * 32) + aKhalf;
                uint32_t addr = r * 128 + (koff ^ ((r & 7) * 16));
                ldsm4(ah[mf], st + A_HI + addr);
            }
#pragma unroll
            for (int np = 0; np < 4; ++np) {
                uint32_t r    = bRow0 + np * 16;
                uint32_t koff = (uint32_t)(ks * 32) + bKhalf;
                uint32_t addr = r * 128 + (koff ^ ((r & 7) * 16));
                ldsm4(bh[np], st + B_HI + addr);
            }
#pragma unroll
            for (int mf = 0; mf < 2; ++mf)
#pragma unroll
                for (int nf = 0; nf < 8; ++nf)
                    hmma(acc[mf][nf], ah[mf],
                         bh[nf >> 1][(nf & 1) * 2], bh[nf >> 1][(nf & 1) * 2 + 1]);
        }

        if ((g & 7) == 7) {
            const int n0 = (g >> 3) * BN;
#pragma unroll
            for (int nf = 0; nf < 8; ++nf) {
                int colb = n0 + wn * 64 + nf * 8 + 2 * (lane & 3);
                float en0 = g_enorm[colb];
                float en1 = g_enorm[colb + 1];
#pragma unroll
                for (int mf = 0; mf < 2; ++mf)
#pragma unroll
                    for (int h = 0; h < 2; ++h) {
                        int s = mf * 2 + h;
                        float sc0 = fmaf(-2.f, acc[mf][nf][2 * h], en0);
                        float sc1 = fmaf(-2.f, acc[mf][nf][2 * h + 1], en1);
                        if (sc0 < m1[s]) { m2[s] = m1[s]; m1[s] = sc0; k1[s] = colb; }
                        else if (sc0 < m2[s]) m2[s] = sc0;
                        if (sc1 < m1[s]) { m2[s] = m1[s]; m1[s] = sc1; k1[s] = colb + 1; }
                        else if (sc1 < m2[s]) m2[s] = sc1;
                        acc[mf][nf][2 * h]     = 0.f;
                        acc[mf][nf][2 * h + 1] = 0.f;
                    }
            }
        }
        __syncthreads();
    }

    // ---- final cross-thread merge -----------------------------------------
    unsigned long long pk[4];
#pragma unroll
    for (int s = 0; s < 4; ++s) {
        int r = wm * 32 + (s >> 1) * 16 + (s & 1) * 8 + (lane >> 2);
        pk[s] = ((unsigned long long)ordf(m1[s]) << 32) | (unsigned)k1[s];
        atomicMin(&best1[r], pk[s]);
    }
    __syncthreads();
#pragma unroll
    for (int s = 0; s < 4; ++s) {
        int r = wm * 32 + (s >> 1) * 16 + (s & 1) * 8 + (lane >> 2);
        unsigned cand = (pk[s] == best1[r]) ? ordf(m2[s]) : ordf(m1[s]);
        atomicMin(&best2[r], cand);
    }
    __syncthreads();
    if (tid < BM) {
        int row = rowBase + tid;
        unsigned long long w = best1[tid];
        g_bestidx[row] = (int)(unsigned)w;
        float bm1 = unordf((unsigned)(w >> 32));
        float bm2 = unordf(best2[tid]);
        if (bm2 - bm1 < EPS_GAP) {
            int p = atomicAdd(&g_unc_count, 1);
            g_unc_rows[p] = row;
            g_unc_best[p] = ~0ull;
        }
    }
}

// ---------- cleanup: exact fp32 rescore, batched 16 rows per pass ----------
__global__ __launch_bounds__(256)
void vq_cleanup_kernel(const float* __restrict__ xs,
                       const float* __restrict__ ew, int K) {
    __shared__ float xrow[CL_ROWS][D_DIM];            // 32 KB
    __shared__ unsigned long long sbest[CL_ROWS];
    const int nslices = K / CL_SLICE;                 // 32
    int cnt = *(volatile int*)&g_unc_count;
    int ngroups = (cnt + CL_ROWS - 1) / CL_ROWS;
    int tasks = ngroups * nslices;

    const int cl = threadIdx.x & 63;                  // 64 code lanes
    const int rl = threadIdx.x >> 6;                  // 4 row quads

    for (int t = blockIdx.x; t < tasks; t += gridDim.x) {
        int grp = t / nslices;
        int sl  = t - grp * nslices;
        int rbase = grp * CL_ROWS;
        int nrows = min(CL_ROWS, cnt - rbase);
        __syncthreads();
        for (int i = threadIdx.x; i < CL_ROWS * (D_DIM / 4); i += 256) {
            int r = i >> 7, c = i & 127;
            int row = g_unc_rows[rbase + ((r < nrows) ? r : 0)];
            ((float4*)xrow[r])[c] = ((const float4*)(xs + (size_t)row * D_DIM))[c];
        }
        if (threadIdx.x < CL_ROWS) sbest[threadIdx.x] = ~0ull;
        __syncthreads();

        int k0 = sl * CL_SLICE + cl;                  // 4 codes, stride 64
        const float4* e0 = (const float4*)(ew + (size_t)(k0)       * D_DIM);
        const float4* e1 = (const float4*)(ew + (size_t)(k0 + 64)  * D_DIM);
        const float4* e2 = (const float4*)(ew + (size_t)(k0 + 128) * D_DIM);
        const float4* e3 = (const float4*)(ew + (size_t)(k0 + 192) * D_DIM);

        float acc[4][4];
#pragma unroll
        for (int q = 0; q < 4; ++q)
#pragma unroll
            for (int j = 0; j < 4; ++j) acc[q][j] = 0.f;

        for (int d = 0; d < D_DIM / 4; ++d) {
            float4 e[4] = { e0[d], e1[d], e2[d], e3[d] };
#pragma unroll
            for (int j = 0; j < 4; ++j) {
                float4 x = ((const float4*)xrow[rl * 4 + j])[d];
#pragma unroll
                for (int q = 0; q < 4; ++q)
                    acc[q][j] = fmaf(e[q].x, x.x, fmaf(e[q].y, x.y,
                                fmaf(e[q].z, x.z, fmaf(e[q].w, x.w, acc[q][j]))));
            }
        }
#pragma unroll
        for (int j = 0; j < 4; ++j) {
            unsigned long long best = ~0ull;
#pragma unroll
            for (int q = 0; q < 4; ++q) {
                int k = k0 + q * 64;
                float sc = g_enorm[k] - 2.f * acc[q][j];
                unsigned long long p =
                    ((unsigned long long)ordf(sc) << 32) | (unsigned)k;
                if (p < best) best = p;
            }
            atomicMin(&sbest[rl * 4 + j], best);
        }
        __syncthreads();
        if (threadIdx.x < (unsigned)nrows)
            atomicMin(&g_unc_best[rbase + threadIdx.x], sbest[threadIdx.x]);
    }
}

// --------------- apply: write resolved indices back ------------------------
__global__ void vq_apply_kernel() {
    int cnt = *(volatile int*)&g_unc_count;
    for (int i = blockIdx.x * blockDim.x + threadIdx.x; i < cnt;
         i += gridDim.x * blockDim.x)
        g_bestidx[g_unc_rows[i]] = (int)(unsigned)g_unc_best[i];
}

// ----------------------- gather + loss ------------------------------------
__global__ __launch_bounds__(256)
void vq_gather_kernel(const float* __restrict__ xs,
                      const float* __restrict__ ew,
                      float* __restrict__ out) {
    __shared__ double red[8];
    double lsum = 0.0;
    int base = blockIdx.x * 32;
    for (int j = threadIdx.x; j < 32 * 128; j += 256) {
        int r = base + (j >> 7);
        int c = j & 127;
        int idx = g_bestidx[r];
        float4 e = *(const float4*)(ew + (size_t)idx * D_DIM + c * 4);
        float4 x = *(const float4*)(xs + (size_t)r * D_DIM + c * 4);
        *(float4*)(out + (size_t)r * D_DIM + c * 4) = e;
        float dx = e.x - x.x, dy = e.y - x.y, dz = e.z - x.z, dw = e.w - x.w;
        lsum += (double)(dx * dx + dy * dy) + (double)(dz * dz + dw * dw);
    }
#pragma unroll
    for (int off = 16; off; off >>= 1) lsum += __shfl_xor_sync(0xffffffffu, lsum, off);
    if ((threadIdx.x & 31) == 0) red[threadIdx.x >> 5] = lsum;
    __syncthreads();
    if (threadIdx.x < 32) {
        double v = (threadIdx.x < 8) ? red[threadIdx.x] : 0.0;
#pragma unroll
        for (int off = 4; off; off >>= 1) v += __shfl_xor_sync(0xffffffffu, v, off);
        if (threadIdx.x == 0) atomicAdd(&g_loss_sum, v);
    }
}

__global__ void vq_finalize_kernel(float* __restrict__ out,
                                   long long n_elems, long long pos) {
    out[pos] = (float)(1.25 * g_loss_sum / (double)n_elems);
}

// ------------------------------ launch -------------------------------------
extern "C" void kernel_launch(void* const* d_in, const int* in_sizes, int n_in,
                              void* d_out, int out_size) {
    const float* xs = (const float*)d_in[0];   // [N, 512]
    const float* ew = (const float*)d_in[1];   // [K, 512]
    float* out = (float*)d_out;

    int N = in_sizes[0] / D_DIM;
    int K = in_sizes[1] / D_DIM;

    cudaFuncSetAttribute(vq_hmma_kernel,
                         cudaFuncAttributeMaxDynamicSharedMemorySize, DSMEM_BYTES);

    vq_convert_kernel<<<4096, 256>>>(xs, ew, N * D_DIM / 2, K * D_DIM / 2);
    vq_prep_kernel<<<(K * 32 + 255) / 256, 256>>>(ew, K);
    vq_hmma_kernel<<<N / BM, THREADS_MAIN, DSMEM_BYTES>>>(K);
    vq_cleanup_kernel<<<1024, 256>>>(xs, ew, K);
    vq_apply_kernel<<<16, 256>>>();
    vq_gather_kernel<<<N / 32, 256>>>(xs, ew, out);

    long long nd = (long long)N * D_DIM;
    if ((long long)out_size > nd) {
        vq_finalize_kernel<<<1, 1>>>(out, nd, nd);
        if ((long long)out_size - 1 != nd)
            vq_finalize_kernel<<<1, 1>>>(out, nd, (long long)out_size - 1);
    }
}

// round 11
// speedup vs baseline: 5.3952x; 1.1947x over previous
#include <cuda_runtime.h>
#include <cuda_fp16.h>
#include <cstdint>

#define D_DIM 512
#define N_TOK 16384
#define K_MAX 8192
#define BM 128
#define BN 128
#define BK 64
#define THREADS_MAIN 256
#define STAGES 3
#define STAGE_BYTES 32768
#define A_HI 0
#define B_HI 16384
#define DSMEM_BYTES (STAGES * STAGE_BYTES + 1024)
#define EPS_GAP 0.12f
#define CL_ROWS 16
#define CL_SLICE 256

// ------------------------- device-global scratch ---------------------------
__device__ __align__(256) __half g_xh[N_TOK * D_DIM];
__device__ __align__(256) __half g_eh[K_MAX * D_DIM];
__device__ float  g_enorm[K_MAX];
__device__ unsigned long long g_p1[2 * N_TOK];     // per-K-half packed min1|idx
__device__ unsigned           g_p2[2 * N_TOK];     // per-K-half ordf(min2)
__device__ int    g_bestidx[N_TOK];
__device__ int    g_unc_rows[N_TOK];
__device__ unsigned long long g_unc_best[N_TOK];
__device__ int    g_unc_count;
__device__ double g_loss_sum;

// ------------------------------ helpers ------------------------------------
__device__ __forceinline__ uint32_t smem_u32(const void* p) {
    uint32_t a;
    asm("{ .reg .u64 t; cvta.to.shared.u64 t, %1; cvt.u32.u64 %0, t; }"
        : "=r"(a) : "l"(p));
    return a;
}
__device__ __forceinline__ void cp_async16(uint32_t dst, const void* src) {
    asm volatile("cp.async.cg.shared.global [%0], [%1], 16;"
                 :: "r"(dst), "l"(src) : "memory");
}
__device__ __forceinline__ void ldsm4(uint32_t* r, uint32_t addr) {
    asm volatile("ldmatrix.sync.aligned.m8n8.x4.shared.b16 {%0,%1,%2,%3}, [%4];"
                 : "=r"(r[0]), "=r"(r[1]), "=r"(r[2]), "=r"(r[3]) : "r"(addr));
}
__device__ __forceinline__ void hmma(float* c, const uint32_t* a,
                                     uint32_t b0, uint32_t b1) {
    asm volatile(
        "mma.sync.aligned.m16n8k16.row.col.f32.f16.f16.f32 "
        "{%0,%1,%2,%3}, {%4,%5,%6,%7}, {%8,%9}, {%0,%1,%2,%3};"
        : "+f"(c[0]), "+f"(c[1]), "+f"(c[2]), "+f"(c[3])
        : "r"(a[0]), "r"(a[1]), "r"(a[2]), "r"(a[3]), "r"(b0), "r"(b1));
}
__device__ __forceinline__ unsigned ordf(float f) {
    unsigned u = __float_as_uint(f);
    return (u & 0x80000000u) ? ~u : (u | 0x80000000u);
}
__device__ __forceinline__ float unordf(unsigned u) {
    unsigned v = (u & 0x80000000u) ? (u & 0x7fffffffu) : ~u;
    return __uint_as_float(v);
}

// --------------------------- convert: fp32 -> fp16 -------------------------
__global__ void vq_convert_kernel(const float* __restrict__ xs,
                                  const float* __restrict__ ew,
                                  int nx2, int ne2) {
    int stride = gridDim.x * blockDim.x;
    for (int i = blockIdx.x * blockDim.x + threadIdx.x; i < nx2; i += stride) {
        float2 v = ((const float2*)xs)[i];
        ((__half2*)g_xh)[i] = __floats2half2_rn(v.x, v.y);
    }
    for (int i = blockIdx.x * blockDim.x + threadIdx.x; i < ne2; i += stride) {
        float2 v = ((const float2*)ew)[i];
        ((__half2*)g_eh)[i] = __floats2half2_rn(v.x, v.y);
    }
}

// --------------------------- prep: enorm + zero scratch --------------------
__global__ void vq_prep_kernel(const float* __restrict__ ew, int K) {
    if (blockIdx.x == 0 && threadIdx.x == 0) { g_loss_sum = 0.0; g_unc_count = 0; }
    int warp = (blockIdx.x * blockDim.x + threadIdx.x) >> 5;
    int lane = threadIdx.x & 31;
    if (warp >= K) return;
    const float4* row = (const float4*)(ew + (size_t)warp * D_DIM);
    float s = 0.f;
#pragma unroll
    for (int it = 0; it < D_DIM / 128; ++it) {
        float4 v = row[lane + 32 * it];
        s += v.x * v.x + v.y * v.y + v.z * v.z + v.w * v.w;
    }
#pragma unroll
    for (int off = 16; off; off >>= 1) s += __shfl_xor_sync(0xffffffffu, s, off);
    if (lane == 0) g_enorm[warp] = s;
}

// --------------------------- chunk loader ----------------------------------
__device__ __forceinline__ void issue_chunk(uint32_t smBase, int g, int tid,
                                            int rowBase, int kOff) {
    const int t = g >> 3, kc = g & 7;
    const int d0 = kc * BK, n0 = kOff + t * BN;
    const uint32_t st = smBase + (uint32_t)(g % STAGES) * STAGE_BYTES;
#pragma unroll
    for (int j = 0; j < 4; ++j) {
        int id  = tid + THREADS_MAIN * j;
        int row = id >> 3, seg = id & 7;
        const __half* src = g_xh + (size_t)(rowBase + row) * D_DIM + d0 + seg * 8;
        uint32_t off = (uint32_t)(row * 128) + ((uint32_t)(seg * 16) ^ ((row & 7) * 16));
        cp_async16(st + A_HI + off, src);
    }
#pragma unroll
    for (int j = 0; j < 4; ++j) {
        int id  = tid + THREADS_MAIN * j;
        int row = id >> 3, seg = id & 7;
        const __half* src = g_eh + (size_t)(n0 + row) * D_DIM + d0 + seg * 8;
        uint32_t off = (uint32_t)(row * 128) + ((uint32_t)(seg * 16) ^ ((row & 7) * 16));
        cp_async16(st + B_HI + off, src);
    }
}

// --------------------------- main HMMA kernel (K-split) --------------------
__global__ __launch_bounds__(THREADS_MAIN, 2)
void vq_hmma_kernel(int K) {
    extern __shared__ __align__(1024) char dsm_raw[];
    __shared__ unsigned long long best1[BM];
    __shared__ unsigned int       best2[BM];

    const int tid  = threadIdx.x;
    const int lane = tid & 31;
    const int warp = tid >> 5;
    const int wm   = warp >> 1;
    const int wn   = warp & 1;
    const int rowBase = blockIdx.x * BM;
    const int kHalf   = blockIdx.y;
    const int kOff    = kHalf * (K >> 1);
    const uint32_t smBase = (smem_u32(dsm_raw) + 1023u) & ~1023u;

    for (int i = tid; i < BM; i += THREADS_MAIN) {
        best1[i] = ~0ull;
        best2[i] = 0xffffffffu;
    }

    float acc[2][8][4];
#pragma unroll
    for (int mf = 0; mf < 2; ++mf)
#pragma unroll
        for (int nf = 0; nf < 8; ++nf)
#pragma unroll
            for (int c = 0; c < 4; ++c) acc[mf][nf][c] = 0.f;

    float m1[4], m2[4];
    int   k1[4];
#pragma unroll
    for (int s = 0; s < 4; ++s) {
        m1[s] = __int_as_float(0x7f800000);
        m2[s] = __int_as_float(0x7f800000);
        k1[s] = 0;
    }

    const uint32_t aRow0  = wm * 32 + (lane & 15);
    const uint32_t aKhalf = (lane & 16) ? 16u : 0u;
    const uint32_t bRow0  = wn * 64 + (lane & 7) + ((lane & 16) >> 1);
    const uint32_t bKhalf = (lane & 8) ? 16u : 0u;

    const int G = ((K >> 1) / BN) * 8;

    issue_chunk(smBase, 0, tid, rowBase, kOff);
    asm volatile("cp.async.commit_group;" ::: "memory");
    issue_chunk(smBase, 1, tid, rowBase, kOff);
    asm volatile("cp.async.commit_group;" ::: "memory");

    for (int g = 0; g < G; ++g) {
        if (g + 2 < G) {
            issue_chunk(smBase, g + 2, tid, rowBase, kOff);
            asm volatile("cp.async.commit_group;" ::: "memory");
            asm volatile("cp.async.wait_group 2;" ::: "memory");
        } else if (g + 1 < G) {
            asm volatile("cp.async.wait_group 1;" ::: "memory");
        } else {
            asm volatile("cp.async.wait_group 0;" ::: "memory");
        }
        __syncthreads();

        const uint32_t st = smBase + (uint32_t)(g % STAGES) * STAGE_BYTES;
#pragma unroll
        for (int ks = 0; ks < 4; ++ks) {
            uint32_t ah[2][4], bh[4][4];
#pragma unroll
            for (int mf = 0; mf < 2; ++mf) {
                uint32_t r    = aRow0 + mf * 16;
                uint32_t koff = (uint32_t)(ks * 32) + aKhalf;
                uint32_t addr = r * 128 + (koff ^ ((r & 7) * 16));
                ldsm4(ah[mf], st + A_HI + addr);
            }
#pragma unroll
            for (int np = 0; np < 4; ++np) {
                uint32_t r    = bRow0 + np * 16;
                uint32_t koff = (uint32_t)(ks * 32) + bKhalf;
                uint32_t addr = r * 128 + (koff ^ ((r & 7) * 16));
                ldsm4(bh[np], st + B_HI + addr);
            }
#pragma unroll
            for (int mf = 0; mf < 2; ++mf)
#pragma unroll
                for (int nf = 0; nf < 8; ++nf)
                    hmma(acc[mf][nf], ah[mf],
                         bh[nf >> 1][(nf & 1) * 2], bh[nf >> 1][(nf & 1) * 2 + 1]);
        }

        if ((g & 7) == 7) {
            const int n0 = kOff + (g >> 3) * BN;
#pragma unroll
            for (int nf = 0; nf < 8; ++nf) {
                int colb = n0 + wn * 64 + nf * 8 + 2 * (lane & 3);
                float en0 = g_enorm[colb];
                float en1 = g_enorm[colb + 1];
#pragma unroll
                for (int mf = 0; mf < 2; ++mf)
#pragma unroll
                    for (int h = 0; h < 2; ++h) {
                        int s = mf * 2 + h;
                        float sc0 = fmaf(-2.f, acc[mf][nf][2 * h], en0);
                        float sc1 = fmaf(-2.f, acc[mf][nf][2 * h + 1], en1);
                        if (sc0 < m1[s]) { m2[s] = m1[s]; m1[s] = sc0; k1[s] = colb; }
                        else if (sc0 < m2[s]) m2[s] = sc0;
                        if (sc1 < m1[s]) { m2[s] = m1[s]; m1[s] = sc1; k1[s] = colb + 1; }
                        else if (sc1 < m2[s]) m2[s] = sc1;
                        acc[mf][nf][2 * h]     = 0.f;
                        acc[mf][nf][2 * h + 1] = 0.f;
                    }
            }
        }
        __syncthreads();
    }

    // ---- CTA-local merge (exact min1/min2 for this K-half) ----------------
    unsigned long long pk[4];
#pragma unroll
    for (int s = 0; s < 4; ++s) {
        int r = wm * 32 + (s >> 1) * 16 + (s & 1) * 8 + (lane >> 2);
        pk[s] = ((unsigned long long)ordf(m1[s]) << 32) | (unsigned)k1[s];
        atomicMin(&best1[r], pk[s]);
    }
    __syncthreads();
#pragma unroll
    for (int s = 0; s < 4; ++s) {
        int r = wm * 32 + (s >> 1) * 16 + (s & 1) * 8 + (lane >> 2);
        unsigned cand = (pk[s] == best1[r]) ? ordf(m2[s]) : ordf(m1[s]);
        atomicMin(&best2[r], cand);
    }
    __syncthreads();
    if (tid < BM) {
        int row = rowBase + tid;
        g_p1[kHalf * N_TOK + row] = best1[tid];
        g_p2[kHalf * N_TOK + row] = best2[tid];
    }
}

// ------------- merge K-halves: final argmin + uncertainty flag -------------
__global__ void vq_merge_kernel(int N) {
    int row = blockIdx.x * blockDim.x + threadIdx.x;
    if (row >= N) return;
    unsigned long long a = g_p1[row], b = g_p1[N_TOK + row];
    unsigned a2 = g_p2[row], b2 = g_p2[N_TOK + row];
    unsigned long long w;
    unsigned m2o;
    if (a <= b) { w = a; m2o = min(a2, (unsigned)(b >> 32)); }
    else        { w = b; m2o = min(b2, (unsigned)(a >> 32)); }
    g_bestidx[row] = (int)(unsigned)w;
    if (unordf(m2o) - unordf((unsigned)(w >> 32)) < EPS_GAP) {
        int p = atomicAdd(&g_unc_count, 1);
        g_unc_rows[p] = row;
        g_unc_best[p] = ~0ull;
    }
}

// ---------- cleanup: exact fp32 rescore, batched + prefetched --------------
__global__ __launch_bounds__(256)
void vq_cleanup_kernel(const float* __restrict__ xs,
                       const float* __restrict__ ew, int K) {
    __shared__ float xrow[CL_ROWS][D_DIM];            // 32 KB
    __shared__ unsigned long long sbest[CL_ROWS];
    const int nslices = K / CL_SLICE;                 // 32
    int cnt = *(volatile int*)&g_unc_count;
    int ngroups = (cnt + CL_ROWS - 1) / CL_ROWS;
    int tasks = ngroups * nslices;

    const int cl = threadIdx.x & 63;                  // 64 code lanes
    const int rl = threadIdx.x >> 6;                  // 4 row quads

    for (int t = blockIdx.x; t < tasks; t += gridDim.x) {
        int grp = t / nslices;
        int sl  = t - grp * nslices;
        int rbase = grp * CL_ROWS;
        int nrows = min(CL_ROWS, cnt - rbase);
        __syncthreads();
        for (int i = threadIdx.x; i < CL_ROWS * (D_DIM / 4); i += 256) {
            int r = i >> 7, c = i & 127;
            int row = g_unc_rows[rbase + ((r < nrows) ? r : 0)];
            ((float4*)xrow[r])[c] = ((const float4*)(xs + (size_t)row * D_DIM))[c];
        }
        if (threadIdx.x < CL_ROWS) sbest[threadIdx.x] = ~0ull;
        __syncthreads();

        int k0 = sl * CL_SLICE + cl;                  // 4 codes, stride 64
        const float4* ep[4] = {
            (const float4*)(ew + (size_t)(k0)       * D_DIM),
            (const float4*)(ew + (size_t)(k0 + 64)  * D_DIM),
            (const float4*)(ew + (size_t)(k0 + 128) * D_DIM),
            (const float4*)(ew + (size_t)(k0 + 192) * D_DIM)
        };

        float acc[4][4];
#pragma unroll
        for (int q = 0; q < 4; ++q)
#pragma unroll
            for (int j = 0; j < 4; ++j) acc[q][j] = 0.f;

        // software-pipelined: prefetch next-d codebook vectors
        float4 e[4] = { ep[0][0], ep[1][0], ep[2][0], ep[3][0] };
#pragma unroll 4
        for (int d = 0; d < D_DIM / 4; ++d) {
            float4 en_[4];
            if (d + 1 < D_DIM / 4) {
#pragma unroll
                for (int q = 0; q < 4; ++q) en_[q] = ep[q][d + 1];
            }
#pragma unroll
            for (int j = 0; j < 4; ++j) {
                float4 x = ((const float4*)xrow[rl * 4 + j])[d];
#pragma unroll
                for (int q = 0; q < 4; ++q)
                    acc[q][j] = fmaf(e[q].x, x.x, fmaf(e[q].y, x.y,
                                fmaf(e[q].z, x.z, fmaf(e[q].w, x.w, acc[q][j]))));
            }
            if (d + 1 < D_DIM / 4) {
#pragma unroll
                for (int q = 0; q < 4; ++q) e[q] = en_[q];
            }
        }
#pragma unroll
        for (int j = 0; j < 4; ++j) {
            unsigned long long best = ~0ull;
#pragma unroll
            for (int q = 0; q < 4; ++q) {
                int k = k0 + q * 64;
                float sc = g_enorm[k] - 2.f * acc[q][j];
                unsigned long long p =
                    ((unsigned long long)ordf(sc) << 32) | (unsigned)k;
                if (p < best) best = p;
            }
            atomicMin(&sbest[rl * 4 + j], best);
        }
        __syncthreads();
        if (threadIdx.x < (unsigned)nrows)
            atomicMin(&g_unc_best[rbase + threadIdx.x], sbest[threadIdx.x]);
    }
}

// --------------- apply: write resolved indices back ------------------------
__global__ void vq_apply_kernel() {
    int cnt = *(volatile int*)&g_unc_count;
    for (int i = blockIdx.x * blockDim.x + threadIdx.x; i < cnt;
         i += gridDim.x * blockDim.x)
        g_bestidx[g_unc_rows[i]] = (int)(unsigned)g_unc_best[i];
}

// ----------------------- gather + loss ------------------------------------
__global__ __launch_bounds__(256)
void vq_gather_kernel(const float* __restrict__ xs,
                      const float* __restrict__ ew,
                      float* __restrict__ out) {
    __shared__ double red[8];
    double lsum = 0.0;
    int base = blockIdx.x * 32;
    for (int j = threadIdx.x; j < 32 * 128; j += 256) {
        int r = base + (j >> 7);
        int c = j & 127;
        int idx = g_bestidx[r];
        float4 e = *(const float4*)(ew + (size_t)idx * D_DIM + c * 4);
        float4 x = *(const float4*)(xs + (size_t)r * D_DIM + c * 4);
        *(float4*)(out + (size_t)r * D_DIM + c * 4) = e;
        float dx = e.x - x.x, dy = e.y - x.y, dz = e.z - x.z, dw = e.w - x.w;
        lsum += (double)(dx * dx + dy * dy) + (double)(dz * dz + dw * dw);
    }
#pragma unroll
    for (int off = 16; off; off >>= 1) lsum += __shfl_xor_sync(0xffffffffu, lsum, off);
    if ((threadIdx.x & 31) == 0) red[threadIdx.x >> 5] = lsum;
    __syncthreads();
    if (threadIdx.x < 32) {
        double v = (threadIdx.x < 8) ? red[threadIdx.x] : 0.0;
#pragma unroll
        for (int off = 4; off; off >>= 1) v += __shfl_xor_sync(0xffffffffu, v, off);
        if (threadIdx.x == 0) atomicAdd(&g_loss_sum, v);
    }
}

__global__ void vq_finalize_kernel(float* __restrict__ out,
                                   long long n_elems, long long pos) {
    out[pos] = (float)(1.25 * g_loss_sum / (double)n_elems);
}

// ------------------------------ launch -------------------------------------
extern "C" void kernel_launch(void* const* d_in, const int* in_sizes, int n_in,
                              void* d_out, int out_size) {
    const float* xs = (const float*)d_in[0];   // [N, 512]
    const float* ew = (const float*)d_in[1];   // [K, 512]
    float* out = (float*)d_out;

    int N = in_sizes[0] / D_DIM;
    int K = in_sizes[1] / D_DIM;

    cudaFuncSetAttribute(vq_hmma_kernel,
                         cudaFuncAttributeMaxDynamicSharedMemorySize, DSMEM_BYTES);

    vq_convert_kernel<<<4096, 256>>>(xs, ew, N * D_DIM / 2, K * D_DIM / 2);
    vq_prep_kernel<<<(K * 32 + 255) / 256, 256>>>(ew, K);
    dim3 grid_main(N / BM, 2);
    vq_hmma_kernel<<<grid_main, THREADS_MAIN, DSMEM_BYTES>>>(K);
    vq_merge_kernel<<<(N + 255) / 256, 256>>>(N);
    vq_cleanup_kernel<<<1024, 256>>>(xs, ew, K);
    vq_apply_kernel<<<16, 256>>>();
    vq_gather_kernel<<<N / 32, 256>>>(xs, ew, out);

    long long nd = (long long)N * D_DIM;
    if ((long long)out_size > nd) {
        vq_finalize_kernel<<<1, 1>>>(out, nd, nd);
        if ((long long)out_size - 1 != nd)
            vq_finalize_kernel<<<1, 1>>>(out, nd, (long long)out_size - 1);
    }
}